// round 17
// baseline (speedup 1.0000x reference)
#include <cuda_runtime.h>
#include <cstdint>

#define N 8192
#define IN_F 512
#define OUT_F 64
#define SS 512

// ---------------- device scratch (static) ----------------
__device__ float g_R[N];                           // exp(-0.8 * s1_i)
__device__ __align__(16) float2 g_EP[N];           // (exp(s2_j), exp(0.2*s2_j))
__device__ __align__(16) float g_part[512 * N];    // 16MB per-block partial colsums
__device__ float g_colsumf[N];
__device__ int   g_hist[65536];                    // bits>>16 histogram

// ---------------- s1,s2 = input @ (W@a)  ->  R_i, (ex_j, ey_j) ----------------
// (R13-R16 fused version; also zeroes the histogram for this replay)
__global__ void k_s(const float* __restrict__ in, const float* __restrict__ W,
                    const float* __restrict__ a) {
    __shared__ float swa[2 * IN_F];
    int t = threadIdx.x;
    if (t < 64) g_hist[blockIdx.x * 64 + t] = 0;   // 1024 blocks x 64 = 65536
#pragma unroll
    for (int half = 0; half < 2; half++) {
        int m = t + half * 256;
        const float4* w4 = (const float4*)(W + m * OUT_F);
        float s1 = 0.f, s2 = 0.f;
#pragma unroll
        for (int q = 0; q < OUT_F / 4; q++) {
            float4 wv = __ldg(w4 + q);
            s1 += wv.x * __ldg(a + 4 * q + 0) + wv.y * __ldg(a + 4 * q + 1)
                + wv.z * __ldg(a + 4 * q + 2) + wv.w * __ldg(a + 4 * q + 3);
            s2 += wv.x * __ldg(a + OUT_F + 4 * q + 0) + wv.y * __ldg(a + OUT_F + 4 * q + 1)
                + wv.z * __ldg(a + OUT_F + 4 * q + 2) + wv.w * __ldg(a + OUT_F + 4 * q + 3);
        }
        swa[m] = s1;
        swa[IN_F + m] = s2;
    }
    __syncthreads();

    int warp = t >> 5, lane = t & 31;
    int row = blockIdx.x * 8 + warp;
    const float* ir = in + (size_t)row * IN_F;
    float s1 = 0.f, s2 = 0.f;
#pragma unroll
    for (int q = 0; q < IN_F / 32; q++) {
        float x = __ldg(ir + q * 32 + lane);
        s1 = fmaf(x, swa[q * 32 + lane], s1);
        s2 = fmaf(x, swa[IN_F + q * 32 + lane], s2);
    }
#pragma unroll
    for (int o = 16; o; o >>= 1) {
        s1 += __shfl_xor_sync(0xFFFFFFFFu, s1, o);
        s2 += __shfl_xor_sync(0xFFFFFFFFu, s2, o);
    }
    if (lane == 0) {
        double d1 = (double)s1, d2 = (double)s2;
        g_R[row] = (float)exp(-0.8 * d1);
        g_EP[row] = make_float2((float)exp(d2), (float)exp(0.2 * d2));
    }
}

// ---------------- two-phase masked-softmax (R12 kernel, VERBATIM, measured 86us) ----
__global__ void __launch_bounds__(512, 1) k_main(const int* __restrict__ adj) {
    __shared__ float sZ[16][16];
    int t = threadIdx.x;
    int warp = t >> 5, lane = t & 31;
    int row0 = blockIdx.x * 16;

    float ex[16], ey[16];
    const float4* ep4 = (const float4*)g_EP;
#pragma unroll
    for (int g = 0; g < 4; g++) {
#pragma unroll
        for (int q = 0; q < 2; q++) {
            float4 v = __ldg(ep4 + g * 1024 + 2 * t + q);
            ex[g * 4 + 2 * q + 0] = v.x; ey[g * 4 + 2 * q + 0] = v.y;
            ex[g * 4 + 2 * q + 1] = v.z; ey[g * 4 + 2 * q + 1] = v.w;
        }
    }

    uint32_t m[16];

    {
        int4 buf[2][4];
#pragma unroll
        for (int g = 0; g < 4; g++) {
            buf[0][g] = __ldg((const int4*)(adj + (size_t)(row0 + 0) * N) + g * 512 + t);
            buf[1][g] = __ldg((const int4*)(adj + (size_t)(row0 + 1) * N) + g * 512 + t);
        }
#pragma unroll
        for (int r = 0; r < 16; r++) {
            float R = __ldg(g_R + row0 + r);
            float z = 0.f;
            uint32_t mask = 0;
#pragma unroll
            for (int g = 0; g < 4; g++) {
                int4 A = buf[r & 1][g];
                float w0 = fmaxf(ex[g * 4 + 0], R * ey[g * 4 + 0]);
                float w1 = fmaxf(ex[g * 4 + 1], R * ey[g * 4 + 1]);
                float w2 = fmaxf(ex[g * 4 + 2], R * ey[g * 4 + 2]);
                float w3 = fmaxf(ex[g * 4 + 3], R * ey[g * 4 + 3]);
                uint32_t b0 = (A.x > 0) ? 1u : 0u;
                uint32_t b1 = (A.y > 0) ? 1u : 0u;
                uint32_t b2 = (A.z > 0) ? 1u : 0u;
                uint32_t b3 = (A.w > 0) ? 1u : 0u;
                mask |= (b0 << (g * 4)) | (b1 << (g * 4 + 1))
                      | (b2 << (g * 4 + 2)) | (b3 << (g * 4 + 3));
                w0 = b0 ? w0 : 0.f;
                w1 = b1 ? w1 : 0.f;
                w2 = b2 ? w2 : 0.f;
                w3 = b3 ? w3 : 0.f;
                z += (w0 + w1) + (w2 + w3);
            }
            if (r < 14) {
                const int4* nb = (const int4*)(adj + (size_t)(row0 + r + 2) * N);
#pragma unroll
                for (int g = 0; g < 4; g++) buf[r & 1][g] = __ldg(nb + g * 512 + t);
            }
            m[r] = mask;
#pragma unroll
            for (int o = 16; o; o >>= 1) z += __shfl_xor_sync(0xFFFFFFFFu, z, o);
            if (lane == 0) sZ[r][warp] = z;
        }
    }
    __syncthreads();

    float acc[16];
#pragma unroll
    for (int k = 0; k < 16; k++) acc[k] = 0.f;

#pragma unroll
    for (int r = 0; r < 16; r++) {
        float zt = 0.f;
#pragma unroll
        for (int q = 0; q < 16; q++) zt += sZ[r][q];
        float invZ = (zt > 0.f) ? (1.0f / zt) : 0.f;
        float R = __ldg(g_R + row0 + r);
        uint32_t mask = m[r];
#pragma unroll
        for (int g = 0; g < 4; g++) {
#pragma unroll
            for (int e = 0; e < 4; e++) {
                int k = g * 4 + e;
                float w0 = fmaxf(ex[k], R * ey[k]);
                float val = (mask >> k) & 1u ? w0 : 0.f;
                acc[k] = fmaf(val, invZ, acc[k]);
            }
        }
    }

    float4* part4 = (float4*)(g_part + (size_t)blockIdx.x * N);
#pragma unroll
    for (int g = 0; g < 4; g++)
        part4[g * 512 + t] = make_float4(acc[g * 4 + 0], acc[g * 4 + 1],
                                         acc[g * 4 + 2], acc[g * 4 + 3]);
}

// ---------------- column reduction (R12 VERBATIM, measured 10us) + histogram ----
__global__ void __launch_bounds__(256) k_reduce() {
    __shared__ float sd[8][32];
    int t = threadIdx.x;
    int v = t & 31;
    int u = t >> 5;
    int c = blockIdx.x * 32 + v;
    float s = 0.f;
    int b0 = u * 64;
#pragma unroll 8
    for (int b = b0; b < b0 + 64; b++)
        s += g_part[(size_t)b * N + c];
    sd[u][v] = s;
    __syncthreads();
    if (u == 0) {
        double tot = 0.0;
#pragma unroll
        for (int q = 0; q < 8; q++) tot += (double)sd[q][v];
        float f = (float)tot;
        g_colsumf[c] = f;
        atomicAdd(&g_hist[__float_as_uint(f) >> 16], 1);   // count-only: deterministic
    }
}

// ---------------- exact top-512: histogram threshold + candidate ranking ----------------
// Threshold bin B = largest bin with suffix-count >= 512. Candidate set
// {j : bits_j >= B<<16} provably contains the top-512, and candidate-internal
// rank == global rank (everything outside is strictly smaller). Exact
// (value desc, index asc) order -> matches jax top_k.
__global__ void __launch_bounds__(1024) k_sel(float* __restrict__ out) {
    __shared__ int csum[1024];
    __shared__ int wsum[32];
    __shared__ uint32_t sTH;
    __shared__ int sC;
    __shared__ uint32_t cb[2048];
    __shared__ int ci[2048];
    int t = threadIdx.x;
    int lane = t & 31, warp = t >> 5;
    if (t == 0) sC = 0;

    // per-thread sum of 64 bins
    int s = 0;
#pragma unroll 8
    for (int k = 0; k < 64; k++) s += g_hist[t * 64 + k];
    csum[t] = s;
    // warp totals
    int ws = s;
#pragma unroll
    for (int o = 16; o; o >>= 1) ws += __shfl_xor_sync(0xFFFFFFFFu, ws, o);
    if (lane == 0) wsum[warp] = ws;
    __syncthreads();

    if (t == 0) {
        int acc = 0, W = 31;
        for (int w = 31; w >= 0; w--) {           // find warp range with the crossing
            if (acc + wsum[w] >= SS) { W = w; break; }
            acc += wsum[w];
        }
        int T = W * 32 + 31;
        for (int q = W * 32 + 31; q >= W * 32; q--) {   // find 64-bin chunk
            if (acc + csum[q] >= SS) { T = q; break; }
            acc += csum[q];
        }
        int b = T * 64 + 63;
        for (; b >= 0; b--) {                     // find exact bin (L1-hot)
            acc += g_hist[b];
            if (acc >= SS) break;
        }
        sTH = (uint32_t)b << 16;
    }
    __syncthreads();

    // compact candidates (order nondeterministic; ranks below are order-independent)
    uint32_t TH = sTH;
#pragma unroll
    for (int q = 0; q < N / 1024; q++) {
        int j = q * 1024 + t;
        uint32_t bits = __float_as_uint(g_colsumf[j]);
        if (bits >= TH) {
            int slot = atomicAdd(&sC, 1);
            if (slot < 2048) { cb[slot] = bits; ci[slot] = j; }
        }
    }
    __syncthreads();

    int C = min(sC, 2048);
    for (int i = t; i < C; i += 1024) {
        uint32_t bi = cb[i];
        int ii = ci[i];
        int r = 0;
        for (int q = 0; q < C; q++) {             // same q across threads -> broadcast
            uint32_t bq = cb[q];
            r += (bq > bi) || (bq == bi && ci[q] < ii);
        }
        if (r < SS) out[r] = (float)ii;           // float index (output dtype is f32)
    }
}

// ---------------- launch (4 kernels) ----------------
extern "C" void kernel_launch(void* const* d_in, const int* in_sizes, int n_in,
                              void* d_out, int out_size) {
    const float* input = nullptr;
    const int*   adj   = nullptr;
    const float* W     = nullptr;
    const float* a     = nullptr;
    for (int i = 0; i < n_in; i++) {
        long long s = in_sizes[i];
        if      (s == (long long)N * IN_F)     input = (const float*)d_in[i];
        else if (s == (long long)N * N)        adj   = (const int*)d_in[i];
        else if (s == (long long)IN_F * OUT_F) W     = (const float*)d_in[i];
        else if (s == 2 * OUT_F)               a     = (const float*)d_in[i];
    }
    if (!input || !adj || !W || !a) {
        input = (const float*)d_in[0];
        adj   = (const int*)d_in[1];
        W     = (const float*)d_in[2];
        a     = (const float*)d_in[3];
    }
    float* out = (float*)d_out;

    k_s<<<N / 8, 256>>>(input, W, a);
    k_main<<<512, 512>>>(adj);
    k_reduce<<<N / 32, 256>>>();
    k_sel<<<1, 1024>>>(out);
}